// round 10
// baseline (speedup 1.0000x reference)
#include <cuda_runtime.h>
#include <cstdint>
#include <math.h>

// ---------------- problem dims (Qwen3-Omni Talker SparseMoeBlock) ------------
#define T_  2048   // tokens
#define H_  2048   // hidden
#define I_  1408   // routed intermediate
#define IS_ 5632   // shared intermediate
#define E_  32     // experts
#define TK_ 4      // top-k

// ---------------- static scratch (no allocations allowed) --------------------
// g_act: max(8192*2816, 2048*11264) = 23,068,672 floats (both equal)
__device__ __align__(16) float g_act[23068672];
// g_h: max(8192*1408, 2048*5632) = 11,534,336 floats (both equal)
__device__ __align__(16) float g_h[11534336];
// g_y: 8192 * 2048 per-pair outputs
__device__ __align__(16) float g_y[16777216];

__device__ int   g_topk_idx[T_ * TK_];
__device__ float g_topk_w[T_ * TK_];
__device__ float g_sgate[T_];
__device__ int   g_cnt[E_];
__device__ int   g_off[E_ + 1];
__device__ int   g_pair_token[T_ * TK_];
__device__ float g_pair_w[T_ * TK_];
__device__ int   g_slot[T_ * TK_];   // slot[t*K+k] = pair index p

// ---------------- router: logits -> softmax top4 -> renorm + sigmoid gate ----
__global__ void router_kernel(const float* __restrict__ x,
                              const float* __restrict__ gate_w,
                              const float* __restrict__ sgate_w) {
    const int t = blockIdx.x;
    const float* xr = x + (size_t)t * H_;
    __shared__ float xs[H_];
    __shared__ float logits[E_];
    __shared__ float red[256];
    const int tid = threadIdx.x;

    for (int i = tid * 4; i < H_; i += 256 * 4) {
        *(float4*)(xs + i) = *(const float4*)(xr + i);
    }
    __syncthreads();

    const int wid = tid >> 5, lane = tid & 31;
    const int ebase = wid * 4;
    float a0 = 0.f, a1 = 0.f, a2 = 0.f, a3 = 0.f;
    for (int h = lane; h < H_; h += 32) {
        const float xv = xs[h];
        const float* gw = gate_w + (size_t)h * E_ + ebase;
        a0 += xv * gw[0]; a1 += xv * gw[1];
        a2 += xv * gw[2]; a3 += xv * gw[3];
    }
    #pragma unroll
    for (int o = 16; o; o >>= 1) {
        a0 += __shfl_xor_sync(~0u, a0, o);
        a1 += __shfl_xor_sync(~0u, a1, o);
        a2 += __shfl_xor_sync(~0u, a2, o);
        a3 += __shfl_xor_sync(~0u, a3, o);
    }
    if (lane == 0) {
        logits[ebase + 0] = a0; logits[ebase + 1] = a1;
        logits[ebase + 2] = a2; logits[ebase + 3] = a3;
    }

    // shared-expert scalar gate: sigmoid(x . shared_gate)
    float p = 0.f;
    for (int h = tid; h < H_; h += 256) p += xs[h] * sgate_w[h];
    red[tid] = p;
    __syncthreads();
    #pragma unroll
    for (int s = 128; s; s >>= 1) {
        if (tid < s) red[tid] += red[tid + s];
        __syncthreads();
    }

    if (tid == 0) {
        g_sgate[t] = 1.f / (1.f + expf(-red[0]));
        float l[E_];
        #pragma unroll
        for (int e = 0; e < E_; e++) l[e] = logits[e];
        int   idx[TK_];
        float val[TK_];
        #pragma unroll
        for (int k = 0; k < TK_; k++) {
            int bi = 0; float bv = -1e30f;
            for (int e = 0; e < E_; e++)
                if (l[e] > bv) { bv = l[e]; bi = e; }
            idx[k] = bi; val[k] = bv; l[bi] = -1e30f;
        }
        // renormalized top-k softmax weights (full-softmax denom cancels)
        const float mx = val[0];
        float s = 0.f, w[TK_];
        #pragma unroll
        for (int k = 0; k < TK_; k++) { w[k] = expf(val[k] - mx); s += w[k]; }
        const float inv = 1.f / s;
        #pragma unroll
        for (int k = 0; k < TK_; k++) {
            g_topk_idx[t * TK_ + k] = idx[k];
            g_topk_w[t * TK_ + k]   = w[k] * inv;
        }
    }
}

// ---------------- per-expert counts + exclusive scan (1 block) ---------------
__global__ void count_scan_kernel() {
    __shared__ int sc[E_];
    const int tid = threadIdx.x;
    if (tid < E_) sc[tid] = 0;
    __syncthreads();
    for (int i = tid; i < T_ * TK_; i += 256)
        atomicAdd(&sc[g_topk_idx[i]], 1);
    __syncthreads();
    if (tid == 0) {
        int run = 0;
        for (int e = 0; e < E_; e++) {
            g_off[e] = run;
            g_cnt[e] = sc[e];
            run += sc[e];
        }
        g_off[E_] = run;
    }
}

// ---------------- deterministic bucketing: 1 warp per expert -----------------
__global__ void bucket_kernel() {
    const int e = blockIdx.x;
    const int lane = threadIdx.x;
    const int base = g_off[e];
    int cnt = 0;
    for (int t0 = 0; t0 < T_; t0 += 32) {
        const int t = t0 + lane;
        int km = -1; float w = 0.f;
        #pragma unroll
        for (int k = 0; k < TK_; k++)
            if (g_topk_idx[t * TK_ + k] == e) { km = k; w = g_topk_w[t * TK_ + k]; }
        const unsigned mask = __ballot_sync(~0u, km >= 0);
        if (km >= 0) {
            const int p = base + cnt + __popc(mask & ((1u << lane) - 1));
            g_pair_token[p] = t;
            g_pair_w[p]     = w;
            g_slot[t * TK_ + km] = p;
        }
        cnt += __popc(mask);
    }
}

// ---------------- TF32 mma GEMM core -----------------------------------------
#define BM 128
#define BN 128
#define BK 32

__device__ __forceinline__ uint32_t f2tf32(float f) {
    uint32_t u;
    asm("cvt.rna.tf32.f32 %0, %1;" : "=r"(u) : "f"(f));
    return u;
}

__device__ __forceinline__ void mma_tf32(float* c, const uint32_t* a, const uint32_t* b) {
    asm volatile(
        "mma.sync.aligned.m16n8k8.row.col.f32.tf32.tf32.f32 "
        "{%0,%1,%2,%3}, {%4,%5,%6,%7}, {%8,%9}, {%0,%1,%2,%3};"
        : "+f"(c[0]), "+f"(c[1]), "+f"(c[2]), "+f"(c[3])
        : "r"(a[0]), "r"(a[1]), "r"(a[2]), "r"(a[3]), "r"(b[0]), "r"(b[1]));
}

// MODE 0: shared GEMM1   act[T,2IS]   = x @ shared_gate_up
// MODE 1: shared GEMM2   out[T,H]     = (hs @ shared_down) * sgate[t]
// MODE 2: routed GEMM1   act[p,2I]    = gather(x) @ w_gate_up[e]   (grouped)
// MODE 3: routed GEMM2   y[p,H]       = (h @ w_down[e]) * pair_w[p](grouped)
template<int MODE>
__global__ void __launch_bounds__(256)
gemm_tf32(const float* __restrict__ Aarg, const float* __restrict__ Barg,
          float* __restrict__ Carg)
{
    constexpr int N   = (MODE == 0) ? 2 * IS_ : (MODE == 2) ? 2 * I_ : H_;
    constexpr int Kd  = (MODE == 0) ? H_ : (MODE == 1) ? IS_ : (MODE == 2) ? H_ : I_;
    constexpr int lda = Kd;   // A row stride equals its K dim in every mode
    constexpr int ldc = N;

    const float* Ab = (MODE == 1 || MODE == 3) ? (const float*)g_h : Aarg;
    float* Cb = (MODE == 1) ? Carg
              : (MODE == 3) ? (float*)g_y
                            : (float*)g_act;

    const int tid = threadIdx.x;
    const int m0 = blockIdx.y * BM;
    const int n0 = blockIdx.x * BN;
    int Mcnt = T_, rowoff = 0;
    const float* B = Barg;
    if (MODE >= 2) {
        const int e = blockIdx.z;
        Mcnt = g_cnt[e];
        if (m0 >= Mcnt) return;          // early-exit empty tiles
        rowoff = g_off[e];
        B = Barg + (size_t)e * ((size_t)Kd * N);
    }

    __shared__ uint32_t As[BM][BK + 4];   // conflict-free A-frag LDS
    __shared__ uint32_t Bs[BK][BN + 8];   // conflict-free B-frag LDS

    // per-thread A staging: thread -> (row mloc, k-half)
    const int mloc  = tid >> 1;
    const int khalf = (tid & 1) * 16;
    const float* Aptr = nullptr;
    {
        const int lr = m0 + mloc;
        if (lr < Mcnt) {
            int grow;
            if (MODE == 2)      grow = g_pair_token[rowoff + lr];
            else if (MODE == 3) grow = rowoff + lr;
            else                grow = lr;
            Aptr = Ab + (size_t)grow * lda;
        }
    }
    const int bkrow = tid >> 5;
    const int bc4   = tid & 31;

    float acc[2][8][4];
    #pragma unroll
    for (int i = 0; i < 2; i++)
        #pragma unroll
        for (int j = 0; j < 8; j++)
            #pragma unroll
            for (int q = 0; q < 4; q++) acc[i][j][q] = 0.f;

    const int lane = tid & 31;
    const int wid  = tid >> 5;
    const int wm = (wid & 3) * 32;   // 4 warps along M
    const int wn = (wid >> 2) * 64;  // 2 warps along N
    const int fc = lane & 3;
    const int fr = lane >> 2;

    const int nK = Kd / BK;
    for (int kt = 0; kt < nK; kt++) {
        // --- stage A (128x32), convert to tf32 (rna rounding: zero-mean err) ---
        #pragma unroll
        for (int q = 0; q < 4; q++) {
            float4 v = make_float4(0.f, 0.f, 0.f, 0.f);
            if (Aptr) v = *(const float4*)(Aptr + kt * BK + khalf + q * 4);
            uint4 u;
            u.x = f2tf32(v.x); u.y = f2tf32(v.y);
            u.z = f2tf32(v.z); u.w = f2tf32(v.w);
            *(uint4*)&As[mloc][khalf + q * 4] = u;
        }
        // --- stage B (32x128) ---
        #pragma unroll
        for (int kp = 0; kp < 4; kp++) {
            const int k = kp * 8 + bkrow;
            const float4 v = *(const float4*)(B + (size_t)(kt * BK + k) * N + n0 + bc4 * 4);
            uint4 u;
            u.x = f2tf32(v.x); u.y = f2tf32(v.y);
            u.z = f2tf32(v.z); u.w = f2tf32(v.w);
            *(uint4*)&Bs[k][bc4 * 4] = u;
        }
        __syncthreads();

        #pragma unroll
        for (int ks = 0; ks < 4; ks++) {
            const int kk = ks * 8;
            uint32_t af[2][4], bf[8][2];
            #pragma unroll
            for (int mt = 0; mt < 2; mt++) {
                const int m = wm + mt * 16 + fr;
                af[mt][0] = As[m][kk + fc];
                af[mt][1] = As[m + 8][kk + fc];
                af[mt][2] = As[m][kk + fc + 4];
                af[mt][3] = As[m + 8][kk + fc + 4];
            }
            #pragma unroll
            for (int nt = 0; nt < 8; nt++) {
                const int n = wn + nt * 8 + fr;
                bf[nt][0] = Bs[kk + fc][n];
                bf[nt][1] = Bs[kk + fc + 4][n];
            }
            #pragma unroll
            for (int mt = 0; mt < 2; mt++)
                #pragma unroll
                for (int nt = 0; nt < 8; nt++)
                    mma_tf32(acc[mt][nt], af[mt], bf[nt]);
        }
        __syncthreads();
    }

    // --- epilogue: per-row scale, guarded rows, float2 stores ---
    #pragma unroll
    for (int mt = 0; mt < 2; mt++) {
        #pragma unroll
        for (int half = 0; half < 2; half++) {
            const int rloc = wm + mt * 16 + fr + half * 8;
            const int lr = m0 + rloc;
            if (lr >= Mcnt) continue;
            float s = 1.f;
            size_t crow = (size_t)lr;
            if (MODE == 1) s = g_sgate[lr];
            if (MODE == 2) crow = (size_t)(rowoff + lr);
            if (MODE == 3) { crow = (size_t)(rowoff + lr); s = g_pair_w[rowoff + lr]; }
            float* Crow = Cb + crow * ldc + n0;
            #pragma unroll
            for (int nt = 0; nt < 8; nt++) {
                const int cc = wn + nt * 8 + fc * 2;
                float2 v;
                v.x = acc[mt][nt][half * 2 + 0] * s;
                v.y = acc[mt][nt][half * 2 + 1] * s;
                *(float2*)(Crow + cc) = v;
            }
        }
    }
}

// ---------------- SiLU(gate) * up: g_act -> g_h --------------------------------
__global__ void silu_mul_kernel(int rows, int inter) {
    const long long n4 = (long long)rows * inter / 4;
    const long long i = (long long)blockIdx.x * blockDim.x + threadIdx.x;
    if (i >= n4) return;
    const long long el = i * 4;
    const int row = (int)(el / inter);
    const int col = (int)(el % inter);
    const float* a = g_act + (size_t)row * (2 * (size_t)inter);
    const float4 g = *(const float4*)(a + col);
    const float4 u = *(const float4*)(a + inter + col);
    float4 o;
    o.x = g.x / (1.f + expf(-g.x)) * u.x;
    o.y = g.y / (1.f + expf(-g.y)) * u.y;
    o.z = g.z / (1.f + expf(-g.z)) * u.z;
    o.w = g.w / (1.f + expf(-g.w)) * u.w;
    *(float4*)(g_h + (size_t)row * inter + col) = o;
}

// ---------------- final combine: out += sum_k y[slot[t][k]] --------------------
__global__ void reduce_kernel(float* __restrict__ out) {
    const int i = blockIdx.x * blockDim.x + threadIdx.x;  // over T*H/4
    const int t = i / (H_ / 4);
    const int c = (i % (H_ / 4)) * 4;
    const int* sl = g_slot + t * TK_;
    float* op = out + (size_t)t * H_ + c;
    float4 a = *(float4*)op;
    #pragma unroll
    for (int k = 0; k < TK_; k++) {
        const float4 y = *(const float4*)(g_y + (size_t)sl[k] * H_ + c);
        a.x += y.x; a.y += y.y; a.z += y.z; a.w += y.w;
    }
    *(float4*)op = a;
}

// ---------------- launch ------------------------------------------------------
extern "C" void kernel_launch(void* const* d_in, const int* in_sizes, int n_in,
                              void* d_out, int out_size) {
    const float* x   = (const float*)d_in[0];
    const float* gw  = (const float*)d_in[1];
    const float* wgu = (const float*)d_in[2];
    const float* wd  = (const float*)d_in[3];
    const float* sgu = (const float*)d_in[4];
    const float* sd  = (const float*)d_in[5];
    const float* sg  = (const float*)d_in[6];
    float* out = (float*)d_out;
    (void)in_sizes; (void)n_in; (void)out_size;

    // router + deterministic bucketing
    router_kernel<<<T_, 256>>>(x, gw, sg);
    count_scan_kernel<<<1, 256>>>();
    bucket_kernel<<<E_, 32>>>();

    // routed experts (grouped, gathered rows)
    gemm_tf32<2><<<dim3(2 * I_ / BN, T_ / BM, E_), 256>>>(x, wgu, nullptr);
    silu_mul_kernel<<<(T_ * TK_ * I_ / 4 + 255) / 256, 256>>>(T_ * TK_, I_);
    gemm_tf32<3><<<dim3(H_ / BN, T_ / BM, E_), 256>>>(nullptr, wd, nullptr);

    // shared expert (dense) -> writes out = shared (sigmoid-gated)
    gemm_tf32<0><<<dim3(2 * IS_ / BN, T_ / BM, 1), 256>>>(x, sgu, nullptr);
    silu_mul_kernel<<<(T_ * IS_ / 4 + 255) / 256, 256>>>(T_, IS_);
    gemm_tf32<1><<<dim3(H_ / BN, T_ / BM, 1), 256>>>(nullptr, sd, out);

    // out += routed combine
    reduce_kernel<<<T_ * H_ / 4 / 256, 256>>>(out);
}

// round 11
// speedup vs baseline: 1.0046x; 1.0046x over previous
#include <cuda_runtime.h>
#include <cstdint>
#include <math.h>

// ---------------- problem dims (Qwen3-Omni Talker SparseMoeBlock) ------------
#define T_  2048   // tokens
#define H_  2048   // hidden
#define I_  1408   // routed intermediate
#define IS_ 5632   // shared intermediate
#define E_  32     // experts
#define TK_ 4      // top-k

// ---------------- static scratch (no allocations allowed) --------------------
__device__ __align__(16) float g_act[23068672];   // max(8192*2816, 2048*11264)
__device__ __align__(16) float g_h[11534336];     // max(8192*1408, 2048*5632)
__device__ __align__(16) float g_y[16777216];     // 8192 * 2048 pair outputs

__device__ int   g_topk_idx[T_ * TK_];
__device__ float g_topk_w[T_ * TK_];
__device__ float g_sgate[T_];
__device__ int   g_cnt[E_];
__device__ int   g_off[E_ + 1];
__device__ int   g_pair_token[T_ * TK_];
__device__ float g_pair_w[T_ * TK_];
__device__ int   g_slot[T_ * TK_];

// ---------------- router: logits -> softmax top4 -> renorm + sigmoid gate ----
__global__ void router_kernel(const float* __restrict__ x,
                              const float* __restrict__ gate_w,
                              const float* __restrict__ sgate_w) {
    const int t = blockIdx.x;
    const float* xr = x + (size_t)t * H_;
    __shared__ float xs[H_];
    __shared__ float logits[E_];
    __shared__ float red[256];
    const int tid = threadIdx.x;

    for (int i = tid * 4; i < H_; i += 256 * 4) {
        *(float4*)(xs + i) = *(const float4*)(xr + i);
    }
    __syncthreads();

    const int wid = tid >> 5, lane = tid & 31;
    const int ebase = wid * 4;
    float a0 = 0.f, a1 = 0.f, a2 = 0.f, a3 = 0.f;
    for (int h = lane; h < H_; h += 32) {
        const float xv = xs[h];
        const float* gw = gate_w + (size_t)h * E_ + ebase;
        a0 += xv * gw[0]; a1 += xv * gw[1];
        a2 += xv * gw[2]; a3 += xv * gw[3];
    }
    #pragma unroll
    for (int o = 16; o; o >>= 1) {
        a0 += __shfl_xor_sync(~0u, a0, o);
        a1 += __shfl_xor_sync(~0u, a1, o);
        a2 += __shfl_xor_sync(~0u, a2, o);
        a3 += __shfl_xor_sync(~0u, a3, o);
    }
    if (lane == 0) {
        logits[ebase + 0] = a0; logits[ebase + 1] = a1;
        logits[ebase + 2] = a2; logits[ebase + 3] = a3;
    }

    float p = 0.f;
    for (int h = tid; h < H_; h += 256) p += xs[h] * sgate_w[h];
    red[tid] = p;
    __syncthreads();
    #pragma unroll
    for (int s = 128; s; s >>= 1) {
        if (tid < s) red[tid] += red[tid + s];
        __syncthreads();
    }

    if (tid == 0) {
        g_sgate[t] = 1.f / (1.f + expf(-red[0]));
        float l[E_];
        #pragma unroll
        for (int e = 0; e < E_; e++) l[e] = logits[e];
        int   idx[TK_];
        float val[TK_];
        #pragma unroll
        for (int k = 0; k < TK_; k++) {
            int bi = 0; float bv = -1e30f;
            for (int e = 0; e < E_; e++)
                if (l[e] > bv) { bv = l[e]; bi = e; }
            idx[k] = bi; val[k] = bv; l[bi] = -1e30f;
        }
        const float mx = val[0];
        float s = 0.f, w[TK_];
        #pragma unroll
        for (int k = 0; k < TK_; k++) { w[k] = expf(val[k] - mx); s += w[k]; }
        const float inv = 1.f / s;
        #pragma unroll
        for (int k = 0; k < TK_; k++) {
            g_topk_idx[t * TK_ + k] = idx[k];
            g_topk_w[t * TK_ + k]   = w[k] * inv;
        }
    }
}

// ---------------- per-expert counts + exclusive scan (1 block) ---------------
__global__ void count_scan_kernel() {
    __shared__ int sc[E_];
    const int tid = threadIdx.x;
    if (tid < E_) sc[tid] = 0;
    __syncthreads();
    for (int i = tid; i < T_ * TK_; i += 256)
        atomicAdd(&sc[g_topk_idx[i]], 1);
    __syncthreads();
    if (tid == 0) {
        int run = 0;
        for (int e = 0; e < E_; e++) {
            g_off[e] = run;
            g_cnt[e] = sc[e];
            run += sc[e];
        }
        g_off[E_] = run;
    }
}

// ---------------- deterministic bucketing: 1 warp per expert -----------------
__global__ void bucket_kernel() {
    const int e = blockIdx.x;
    const int lane = threadIdx.x;
    const int base = g_off[e];
    int cnt = 0;
    for (int t0 = 0; t0 < T_; t0 += 32) {
        const int t = t0 + lane;
        int km = -1; float w = 0.f;
        #pragma unroll
        for (int k = 0; k < TK_; k++)
            if (g_topk_idx[t * TK_ + k] == e) { km = k; w = g_topk_w[t * TK_ + k]; }
        const unsigned mask = __ballot_sync(~0u, km >= 0);
        if (km >= 0) {
            const int p = base + cnt + __popc(mask & ((1u << lane) - 1));
            g_pair_token[p] = t;
            g_pair_w[p]     = w;
            g_slot[t * TK_ + km] = p;
        }
        cnt += __popc(mask);
    }
}

// ---------------- TF32 mma GEMM core (cp.async double-buffered) --------------
#define BM 128
#define BN 128
#define BK 32
#define ASTRIDE 36                 // conflict-free A pad (banks fr*4+fc)
#define BSTRIDE 136                // conflict-free B pad (banks fc*8+fr)
#define ABUF (BM * ASTRIDE)        // 4608 floats per buffer
#define BBUF (BK * BSTRIDE)        // 4352 floats per buffer
#define SMEM_BYTES ((2 * ABUF + 2 * BBUF) * 4)   // 71680 bytes

__device__ __forceinline__ uint32_t f2tf32(float f) {
    uint32_t u;
    asm("cvt.rna.tf32.f32 %0, %1;" : "=r"(u) : "f"(f));
    return u;
}

__device__ __forceinline__ void mma_tf32(float* c, const uint32_t* a, const uint32_t* b) {
    asm volatile(
        "mma.sync.aligned.m16n8k8.row.col.f32.tf32.tf32.f32 "
        "{%0,%1,%2,%3}, {%4,%5,%6,%7}, {%8,%9}, {%0,%1,%2,%3};"
        : "+f"(c[0]), "+f"(c[1]), "+f"(c[2]), "+f"(c[3])
        : "r"(a[0]), "r"(a[1]), "r"(a[2]), "r"(a[3]), "r"(b[0]), "r"(b[1]));
}

__device__ __forceinline__ void cp16(uint32_t dst, const float* src) {
    asm volatile("cp.async.cg.shared.global [%0], [%1], 16;" :: "r"(dst), "l"(src));
}

// MODE 0: shared GEMM1   act[T,2IS]   = x @ shared_gate_up
// MODE 1: shared GEMM2   out[T,H]     = (hs @ shared_down) * sgate[t]
// MODE 2: routed GEMM1   act[p,2I]    = gather(x) @ w_gate_up[e]   (grouped)
// MODE 3: routed GEMM2   y[p,H]       = (h @ w_down[e]) * pair_w[p](grouped)
template<int MODE>
__global__ void __launch_bounds__(128)
gemm_tf32(const float* __restrict__ Aarg, const float* __restrict__ Barg,
          float* __restrict__ Carg)
{
    constexpr int N   = (MODE == 0) ? 2 * IS_ : (MODE == 2) ? 2 * I_ : H_;
    constexpr int Kd  = (MODE == 0) ? H_ : (MODE == 1) ? IS_ : (MODE == 2) ? H_ : I_;
    constexpr int ldc = N;

    const float* Ab = (MODE == 1 || MODE == 3) ? (const float*)g_h : Aarg;
    float* Cb = (MODE == 1) ? Carg
              : (MODE == 3) ? (float*)g_y
                            : (float*)g_act;

    const int tid = threadIdx.x;
    const int m0 = blockIdx.y * BM;
    const int n0 = blockIdx.x * BN;
    int Mcnt = T_, rowoff = 0;
    const float* B = Barg;
    if (MODE >= 2) {
        const int e = blockIdx.z;
        Mcnt = g_cnt[e];
        if (m0 >= Mcnt) return;          // early-exit empty tiles
        rowoff = g_off[e];
        B = Barg + (size_t)e * ((size_t)Kd * N);
    }

    extern __shared__ float sm[];
    float* Asm = sm;                  // 2 x [BM][ASTRIDE]
    float* Bsm = sm + 2 * ABUF;       // 2 x [BK][BSTRIDE]

    // A staging: thread t owns logical row m0+t (clamped; masked in epilogue)
    const float* Aptr;
    {
        int lr = m0 + tid;
        if (lr >= Mcnt) lr = Mcnt - 1;   // safe dummy (finite data, never stored)
        int grow;
        if (MODE == 2)      grow = g_pair_token[rowoff + lr];
        else if (MODE == 3) grow = rowoff + lr;
        else                grow = lr;
        Aptr = Ab + (size_t)grow * Kd;
    }

    float acc[4][8][4];
    #pragma unroll
    for (int i = 0; i < 4; i++)
        #pragma unroll
        for (int j = 0; j < 8; j++)
            #pragma unroll
            for (int q = 0; q < 4; q++) acc[i][j][q] = 0.f;

    const int lane = tid & 31;
    const int wid  = tid >> 5;
    const int wm = (wid & 1) * 64;     // 2 warps along M (64 rows each)
    const int wn = (wid >> 1) * 64;    // 2 warps along N (64 cols each)
    const int fr = lane >> 2;
    const int fc = lane & 3;

    const uint32_t a_sbase =
        (uint32_t)__cvta_generic_to_shared(Asm + tid * ASTRIDE);
    const int nK = Kd / BK;

    // async stage of one K-tile into buffer `buf`
    auto stage = [&](int kt, int buf) {
        const float* asrc = Aptr + kt * BK;
        const uint32_t ad = a_sbase + (uint32_t)(buf * ABUF * 4);
        #pragma unroll
        for (int q = 0; q < 8; q++)
            cp16(ad + q * 16, asrc + q * 4);
        #pragma unroll
        for (int i = 0; i < 8; i++) {
            const int f = i * 128 + tid;
            const int row = f >> 5, c4 = f & 31;
            const uint32_t bd = (uint32_t)__cvta_generic_to_shared(
                Bsm + buf * BBUF + row * BSTRIDE + c4 * 4);
            cp16(bd, B + (size_t)(kt * BK + row) * N + n0 + c4 * 4);
        }
        asm volatile("cp.async.commit_group;");
    };

    stage(0, 0);
    asm volatile("cp.async.wait_group 0;");
    __syncthreads();

    for (int kt = 0; kt < nK; kt++) {
        if (kt + 1 < nK) stage(kt + 1, (kt + 1) & 1);

        const float* A_ = Asm + (kt & 1) * ABUF;
        const float* B_ = Bsm + (kt & 1) * BBUF;

        #pragma unroll
        for (int ks = 0; ks < 4; ks++) {
            const int kk = ks * 8;
            uint32_t af[4][4], bf[8][2];
            #pragma unroll
            for (int mt = 0; mt < 4; mt++) {
                const int m = wm + mt * 16 + fr;
                af[mt][0] = f2tf32(A_[m * ASTRIDE + kk + fc]);
                af[mt][1] = f2tf32(A_[(m + 8) * ASTRIDE + kk + fc]);
                af[mt][2] = f2tf32(A_[m * ASTRIDE + kk + fc + 4]);
                af[mt][3] = f2tf32(A_[(m + 8) * ASTRIDE + kk + fc + 4]);
            }
            #pragma unroll
            for (int nt = 0; nt < 8; nt++) {
                const int n = wn + nt * 8 + fr;
                bf[nt][0] = f2tf32(B_[(kk + fc) * BSTRIDE + n]);
                bf[nt][1] = f2tf32(B_[(kk + fc + 4) * BSTRIDE + n]);
            }
            #pragma unroll
            for (int mt = 0; mt < 4; mt++)
                #pragma unroll
                for (int nt = 0; nt < 8; nt++)
                    mma_tf32(acc[mt][nt], af[mt], bf[nt]);
        }

        asm volatile("cp.async.wait_group 0;");
        __syncthreads();
    }

    // --- epilogue: per-row scale, guarded rows, float2 stores ---
    #pragma unroll
    for (int mt = 0; mt < 4; mt++) {
        #pragma unroll
        for (int half = 0; half < 2; half++) {
            const int rloc = wm + mt * 16 + fr + half * 8;
            const int lr = m0 + rloc;
            if (lr >= Mcnt) continue;
            float s = 1.f;
            size_t crow = (size_t)lr;
            if (MODE == 1) s = g_sgate[lr];
            if (MODE == 2) crow = (size_t)(rowoff + lr);
            if (MODE == 3) { crow = (size_t)(rowoff + lr); s = g_pair_w[rowoff + lr]; }
            float* Crow = Cb + crow * ldc + n0;
            #pragma unroll
            for (int nt = 0; nt < 8; nt++) {
                const int cc = wn + nt * 8 + fc * 2;
                float2 v;
                v.x = acc[mt][nt][half * 2 + 0] * s;
                v.y = acc[mt][nt][half * 2 + 1] * s;
                *(float2*)(Crow + cc) = v;
            }
        }
    }
}

// ---------------- SiLU(gate) * up: g_act -> g_h --------------------------------
__global__ void silu_mul_kernel(int rows, int inter) {
    const long long n4 = (long long)rows * inter / 4;
    const long long i = (long long)blockIdx.x * blockDim.x + threadIdx.x;
    if (i >= n4) return;
    const long long el = i * 4;
    const int row = (int)(el / inter);
    const int col = (int)(el % inter);
    const float* a = g_act + (size_t)row * (2 * (size_t)inter);
    const float4 g = *(const float4*)(a + col);
    const float4 u = *(const float4*)(a + inter + col);
    float4 o;
    o.x = g.x / (1.f + expf(-g.x)) * u.x;
    o.y = g.y / (1.f + expf(-g.y)) * u.y;
    o.z = g.z / (1.f + expf(-g.z)) * u.z;
    o.w = g.w / (1.f + expf(-g.w)) * u.w;
    *(float4*)(g_h + (size_t)row * inter + col) = o;
}

// ---------------- final combine: out += sum_k y[slot[t][k]] --------------------
__global__ void reduce_kernel(float* __restrict__ out) {
    const int i = blockIdx.x * blockDim.x + threadIdx.x;  // over T*H/4
    const int t = i / (H_ / 4);
    const int c = (i % (H_ / 4)) * 4;
    const int* sl = g_slot + t * TK_;
    float* op = out + (size_t)t * H_ + c;
    float4 a = *(float4*)op;
    #pragma unroll
    for (int k = 0; k < TK_; k++) {
        const float4 y = *(const float4*)(g_y + (size_t)sl[k] * H_ + c);
        a.x += y.x; a.y += y.y; a.z += y.z; a.w += y.w;
    }
    *(float4*)op = a;
}

// ---------------- launch ------------------------------------------------------
extern "C" void kernel_launch(void* const* d_in, const int* in_sizes, int n_in,
                              void* d_out, int out_size) {
    const float* x   = (const float*)d_in[0];
    const float* gw  = (const float*)d_in[1];
    const float* wgu = (const float*)d_in[2];
    const float* wd  = (const float*)d_in[3];
    const float* sgu = (const float*)d_in[4];
    const float* sd  = (const float*)d_in[5];
    const float* sg  = (const float*)d_in[6];
    float* out = (float*)d_out;
    (void)in_sizes; (void)n_in; (void)out_size;

    // opt-in to >48KB dynamic smem (idempotent; not a stream op)
    cudaFuncSetAttribute(gemm_tf32<0>, cudaFuncAttributeMaxDynamicSharedMemorySize, SMEM_BYTES);
    cudaFuncSetAttribute(gemm_tf32<1>, cudaFuncAttributeMaxDynamicSharedMemorySize, SMEM_BYTES);
    cudaFuncSetAttribute(gemm_tf32<2>, cudaFuncAttributeMaxDynamicSharedMemorySize, SMEM_BYTES);
    cudaFuncSetAttribute(gemm_tf32<3>, cudaFuncAttributeMaxDynamicSharedMemorySize, SMEM_BYTES);

    // router + deterministic bucketing
    router_kernel<<<T_, 256>>>(x, gw, sg);
    count_scan_kernel<<<1, 256>>>();
    bucket_kernel<<<E_, 32>>>();

    // routed experts (grouped, gathered rows)
    gemm_tf32<2><<<dim3(2 * I_ / BN, T_ / BM, E_), 128, SMEM_BYTES>>>(x, wgu, nullptr);
    silu_mul_kernel<<<(T_ * TK_ * I_ / 4 + 255) / 256, 256>>>(T_ * TK_, I_);
    gemm_tf32<3><<<dim3(H_ / BN, T_ / BM, E_), 128, SMEM_BYTES>>>(nullptr, wd, nullptr);

    // shared expert (dense) -> writes out = shared (sigmoid-gated)
    gemm_tf32<0><<<dim3(2 * IS_ / BN, T_ / BM, 1), 128, SMEM_BYTES>>>(x, sgu, nullptr);
    silu_mul_kernel<<<(T_ * IS_ / 4 + 255) / 256, 256>>>(T_, IS_);
    gemm_tf32<1><<<dim3(H_ / BN, T_ / BM, 1), 128, SMEM_BYTES>>>(nullptr, sd, out);

    // out += routed combine
    reduce_kernel<<<T_ * H_ / 4 / 256, 256>>>(out);
}

// round 12
// speedup vs baseline: 1.0069x; 1.0022x over previous
#include <cuda_runtime.h>
#include <cstdint>
#include <math.h>

// ---------------- problem dims (Qwen3-Omni Talker SparseMoeBlock) ------------
#define T_  2048   // tokens
#define H_  2048   // hidden
#define I_  1408   // routed intermediate
#define IS_ 5632   // shared intermediate
#define E_  32     // experts
#define TK_ 4      // top-k

// ---------------- static scratch (no allocations allowed) --------------------
__device__ __align__(16) float g_act[23068672];   // max(8192*2816, 2048*11264)
__device__ __align__(16) float g_h[11534336];     // max(8192*1408, 2048*5632)
__device__ __align__(16) float g_y[16777216];     // 8192 * 2048 pair outputs

__device__ int   g_topk_idx[T_ * TK_];
__device__ float g_topk_w[T_ * TK_];
__device__ float g_sgate[T_];
__device__ int   g_cnt[E_];
__device__ int   g_off[E_ + 1];
__device__ int   g_pair_token[T_ * TK_];
__device__ float g_pair_w[T_ * TK_];
__device__ int   g_slot[T_ * TK_];

// ---------------- router: logits -> softmax top4 -> renorm + sigmoid gate ----
__global__ void router_kernel(const float* __restrict__ x,
                              const float* __restrict__ gate_w,
                              const float* __restrict__ sgate_w) {
    const int t = blockIdx.x;
    const float* xr = x + (size_t)t * H_;
    __shared__ float xs[H_];
    __shared__ float logits[E_];
    __shared__ float red[256];
    const int tid = threadIdx.x;

    for (int i = tid * 4; i < H_; i += 256 * 4) {
        *(float4*)(xs + i) = *(const float4*)(xr + i);
    }
    __syncthreads();

    const int wid = tid >> 5, lane = tid & 31;
    const int ebase = wid * 4;
    float a0 = 0.f, a1 = 0.f, a2 = 0.f, a3 = 0.f;
    for (int h = lane; h < H_; h += 32) {
        const float xv = xs[h];
        const float* gw = gate_w + (size_t)h * E_ + ebase;
        a0 += xv * gw[0]; a1 += xv * gw[1];
        a2 += xv * gw[2]; a3 += xv * gw[3];
    }
    #pragma unroll
    for (int o = 16; o; o >>= 1) {
        a0 += __shfl_xor_sync(~0u, a0, o);
        a1 += __shfl_xor_sync(~0u, a1, o);
        a2 += __shfl_xor_sync(~0u, a2, o);
        a3 += __shfl_xor_sync(~0u, a3, o);
    }
    if (lane == 0) {
        logits[ebase + 0] = a0; logits[ebase + 1] = a1;
        logits[ebase + 2] = a2; logits[ebase + 3] = a3;
    }

    float p = 0.f;
    for (int h = tid; h < H_; h += 256) p += xs[h] * sgate_w[h];
    red[tid] = p;
    __syncthreads();
    #pragma unroll
    for (int s = 128; s; s >>= 1) {
        if (tid < s) red[tid] += red[tid + s];
        __syncthreads();
    }

    if (tid == 0) {
        g_sgate[t] = 1.f / (1.f + expf(-red[0]));
        float l[E_];
        #pragma unroll
        for (int e = 0; e < E_; e++) l[e] = logits[e];
        int   idx[TK_];
        float val[TK_];
        #pragma unroll
        for (int k = 0; k < TK_; k++) {
            int bi = 0; float bv = -1e30f;
            for (int e = 0; e < E_; e++)
                if (l[e] > bv) { bv = l[e]; bi = e; }
            idx[k] = bi; val[k] = bv; l[bi] = -1e30f;
        }
        const float mx = val[0];
        float s = 0.f, w[TK_];
        #pragma unroll
        for (int k = 0; k < TK_; k++) { w[k] = expf(val[k] - mx); s += w[k]; }
        const float inv = 1.f / s;
        #pragma unroll
        for (int k = 0; k < TK_; k++) {
            g_topk_idx[t * TK_ + k] = idx[k];
            g_topk_w[t * TK_ + k]   = w[k] * inv;
        }
    }
}

// ---------------- per-expert counts + exclusive scan (1 block) ---------------
__global__ void count_scan_kernel() {
    __shared__ int sc[E_];
    const int tid = threadIdx.x;
    if (tid < E_) sc[tid] = 0;
    __syncthreads();
    for (int i = tid; i < T_ * TK_; i += 256)
        atomicAdd(&sc[g_topk_idx[i]], 1);
    __syncthreads();
    if (tid == 0) {
        int run = 0;
        for (int e = 0; e < E_; e++) {
            g_off[e] = run;
            g_cnt[e] = sc[e];
            run += sc[e];
        }
        g_off[E_] = run;
    }
}

// ---------------- deterministic bucketing: 1 warp per expert -----------------
__global__ void bucket_kernel() {
    const int e = blockIdx.x;
    const int lane = threadIdx.x;
    const int base = g_off[e];
    int cnt = 0;
    for (int t0 = 0; t0 < T_; t0 += 32) {
        const int t = t0 + lane;
        int km = -1; float w = 0.f;
        #pragma unroll
        for (int k = 0; k < TK_; k++)
            if (g_topk_idx[t * TK_ + k] == e) { km = k; w = g_topk_w[t * TK_ + k]; }
        const unsigned mask = __ballot_sync(~0u, km >= 0);
        if (km >= 0) {
            const int p = base + cnt + __popc(mask & ((1u << lane) - 1));
            g_pair_token[p] = t;
            g_pair_w[p]     = w;
            g_slot[t * TK_ + km] = p;
        }
        cnt += __popc(mask);
    }
}

// ---------------- TF32 mma GEMM core (cp.async double-buffered) --------------
#define BM 128
#define BN 128
#define BK 32
#define ASTRIDE 36                 // conflict-free A pad (banks fr*4+fc)
#define BSTRIDE 136                // conflict-free B pad (banks fc*8+fr)
#define ABUF (BM * ASTRIDE)        // 4608 floats per buffer
#define BBUF (BK * BSTRIDE)        // 4352 floats per buffer
#define SMEM_BYTES ((2 * ABUF + 2 * BBUF) * 4)   // 71680 bytes

__device__ __forceinline__ uint32_t f2tf32(float f) {
    uint32_t u;
    asm("cvt.rna.tf32.f32 %0, %1;" : "=r"(u) : "f"(f));
    return u;
}

__device__ __forceinline__ void mma_tf32(float* c, const uint32_t* a, const uint32_t* b) {
    asm volatile(
        "mma.sync.aligned.m16n8k8.row.col.f32.tf32.tf32.f32 "
        "{%0,%1,%2,%3}, {%4,%5,%6,%7}, {%8,%9}, {%0,%1,%2,%3};"
        : "+f"(c[0]), "+f"(c[1]), "+f"(c[2]), "+f"(c[3])
        : "r"(a[0]), "r"(a[1]), "r"(a[2]), "r"(a[3]), "r"(b[0]), "r"(b[1]));
}

__device__ __forceinline__ void cp16(uint32_t dst, const float* src) {
    asm volatile("cp.async.cg.shared.global [%0], [%1], 16;" :: "r"(dst), "l"(src));
}

// MODE 0: shared GEMM1   act[T,2IS]   = x @ shared_gate_up
// MODE 1: shared GEMM2   out[T,H]     = (hs @ shared_down) * sgate[t]
// MODE 2: routed GEMM1   act[p,2I]    = gather(x) @ w_gate_up[e]   (grouped)
// MODE 3: routed GEMM2   y[p,H]       = (h @ w_down[e]) * pair_w[p](grouped)
template<int MODE>
__global__ void __launch_bounds__(128)
gemm_tf32(const float* __restrict__ Aarg, const float* __restrict__ Barg,
          float* __restrict__ Carg)
{
    constexpr int N   = (MODE == 0) ? 2 * IS_ : (MODE == 2) ? 2 * I_ : H_;
    constexpr int Kd  = (MODE == 0) ? H_ : (MODE == 1) ? IS_ : (MODE == 2) ? H_ : I_;
    constexpr int ldc = N;

    const float* Ab = (MODE == 1 || MODE == 3) ? (const float*)g_h : Aarg;
    float* Cb = (MODE == 1) ? Carg
              : (MODE == 3) ? (float*)g_y
                            : (float*)g_act;

    const int tid = threadIdx.x;
    const int m0 = blockIdx.y * BM;
    const int n0 = blockIdx.x * BN;
    int Mcnt = T_, rowoff = 0;
    const float* B = Barg;
    if (MODE >= 2) {
        const int e = blockIdx.z;
        Mcnt = g_cnt[e];
        if (m0 >= Mcnt) return;          // early-exit empty tiles
        rowoff = g_off[e];
        B = Barg + (size_t)e * ((size_t)Kd * N);
    }

    extern __shared__ float sm[];
    float* Asm = sm;                  // 2 x [BM][ASTRIDE]
    float* Bsm = sm + 2 * ABUF;       // 2 x [BK][BSTRIDE]

    // A staging: thread t owns logical row m0+t (clamped; masked in epilogue)
    const float* Aptr;
    {
        int lr = m0 + tid;
        if (lr >= Mcnt) lr = Mcnt - 1;   // safe dummy (finite data, never stored)
        int grow;
        if (MODE == 2)      grow = g_pair_token[rowoff + lr];
        else if (MODE == 3) grow = rowoff + lr;
        else                grow = lr;
        Aptr = Ab + (size_t)grow * Kd;
    }

    float acc[4][8][4];
    #pragma unroll
    for (int i = 0; i < 4; i++)
        #pragma unroll
        for (int j = 0; j < 8; j++)
            #pragma unroll
            for (int q = 0; q < 4; q++) acc[i][j][q] = 0.f;

    const int lane = tid & 31;
    const int wid  = tid >> 5;
    const int wm = (wid & 1) * 64;     // 2 warps along M (64 rows each)
    const int wn = (wid >> 1) * 64;    // 2 warps along N (64 cols each)
    const int fr = lane >> 2;
    const int fc = lane & 3;

    const uint32_t a_sbase =
        (uint32_t)__cvta_generic_to_shared(Asm + tid * ASTRIDE);
    const int nK = Kd / BK;

    // async stage of one K-tile into buffer `buf`
    auto stage = [&](int kt, int buf) {
        const float* asrc = Aptr + kt * BK;
        const uint32_t ad = a_sbase + (uint32_t)(buf * ABUF * 4);
        #pragma unroll
        for (int q = 0; q < 8; q++)
            cp16(ad + q * 16, asrc + q * 4);
        #pragma unroll
        for (int i = 0; i < 8; i++) {
            const int f = i * 128 + tid;
            const int row = f >> 5, c4 = f & 31;
            const uint32_t bd = (uint32_t)__cvta_generic_to_shared(
                Bsm + buf * BBUF + row * BSTRIDE + c4 * 4);
            cp16(bd, B + (size_t)(kt * BK + row) * N + n0 + c4 * 4);
        }
        asm volatile("cp.async.commit_group;");
    };

    stage(0, 0);
    asm volatile("cp.async.wait_group 0;");
    __syncthreads();

    for (int kt = 0; kt < nK; kt++) {
        if (kt + 1 < nK) stage(kt + 1, (kt + 1) & 1);

        const float* A_ = Asm + (kt & 1) * ABUF;
        const float* B_ = Bsm + (kt & 1) * BBUF;

        #pragma unroll
        for (int ks = 0; ks < 4; ks++) {
            const int kk = ks * 8;
            uint32_t af[4][4], bf[8][2];
            #pragma unroll
            for (int mt = 0; mt < 4; mt++) {
                const int m = wm + mt * 16 + fr;
                af[mt][0] = f2tf32(A_[m * ASTRIDE + kk + fc]);
                af[mt][1] = f2tf32(A_[(m + 8) * ASTRIDE + kk + fc]);
                af[mt][2] = f2tf32(A_[m * ASTRIDE + kk + fc + 4]);
                af[mt][3] = f2tf32(A_[(m + 8) * ASTRIDE + kk + fc + 4]);
            }
            #pragma unroll
            for (int nt = 0; nt < 8; nt++) {
                const int n = wn + nt * 8 + fr;
                bf[nt][0] = f2tf32(B_[(kk + fc) * BSTRIDE + n]);
                bf[nt][1] = f2tf32(B_[(kk + fc + 4) * BSTRIDE + n]);
            }
            #pragma unroll
            for (int mt = 0; mt < 4; mt++)
                #pragma unroll
                for (int nt = 0; nt < 8; nt++)
                    mma_tf32(acc[mt][nt], af[mt], bf[nt]);
        }

        asm volatile("cp.async.wait_group 0;");
        __syncthreads();
    }

    // --- epilogue: per-row scale, guarded rows, float2 stores ---
    #pragma unroll
    for (int mt = 0; mt < 4; mt++) {
        #pragma unroll
        for (int half = 0; half < 2; half++) {
            const int rloc = wm + mt * 16 + fr + half * 8;
            const int lr = m0 + rloc;
            if (lr >= Mcnt) continue;
            float s = 1.f;
            size_t crow = (size_t)lr;
            if (MODE == 1) s = g_sgate[lr];
            if (MODE == 2) crow = (size_t)(rowoff + lr);
            if (MODE == 3) { crow = (size_t)(rowoff + lr); s = g_pair_w[rowoff + lr]; }
            float* Crow = Cb + crow * ldc + n0;
            #pragma unroll
            for (int nt = 0; nt < 8; nt++) {
                const int cc = wn + nt * 8 + fc * 2;
                float2 v;
                v.x = acc[mt][nt][half * 2 + 0] * s;
                v.y = acc[mt][nt][half * 2 + 1] * s;
                *(float2*)(Crow + cc) = v;
            }
        }
    }
}

// ---------------- SiLU(gate) * up: g_act -> g_h --------------------------------
__global__ void silu_mul_kernel(int rows, int inter) {
    const long long n4 = (long long)rows * inter / 4;
    const long long i = (long long)blockIdx.x * blockDim.x + threadIdx.x;
    if (i >= n4) return;
    const long long el = i * 4;
    const int row = (int)(el / inter);
    const int col = (int)(el % inter);
    const float* a = g_act + (size_t)row * (2 * (size_t)inter);
    const float4 g = *(const float4*)(a + col);
    const float4 u = *(const float4*)(a + inter + col);
    float4 o;
    o.x = g.x / (1.f + expf(-g.x)) * u.x;
    o.y = g.y / (1.f + expf(-g.y)) * u.y;
    o.z = g.z / (1.f + expf(-g.z)) * u.z;
    o.w = g.w / (1.f + expf(-g.w)) * u.w;
    *(float4*)(g_h + (size_t)row * inter + col) = o;
}

// ---------------- final combine: out += sum_k y[slot[t][k]] --------------------
__global__ void reduce_kernel(float* __restrict__ out) {
    const int i = blockIdx.x * blockDim.x + threadIdx.x;  // over T*H/4
    const int t = i / (H_ / 4);
    const int c = (i % (H_ / 4)) * 4;
    const int* sl = g_slot + t * TK_;
    float* op = out + (size_t)t * H_ + c;
    float4 a = *(float4*)op;
    #pragma unroll
    for (int k = 0; k < TK_; k++) {
        const float4 y = *(const float4*)(g_y + (size_t)sl[k] * H_ + c);
        a.x += y.x; a.y += y.y; a.z += y.z; a.w += y.w;
    }
    *(float4*)op = a;
}

// ---------------- launch ------------------------------------------------------
extern "C" void kernel_launch(void* const* d_in, const int* in_sizes, int n_in,
                              void* d_out, int out_size) {
    const float* x   = (const float*)d_in[0];
    const float* gw  = (const float*)d_in[1];
    const float* wgu = (const float*)d_in[2];
    const float* wd  = (const float*)d_in[3];
    const float* sgu = (const float*)d_in[4];
    const float* sd  = (const float*)d_in[5];
    const float* sg  = (const float*)d_in[6];
    float* out = (float*)d_out;
    (void)in_sizes; (void)n_in; (void)out_size;

    // opt-in to >48KB dynamic smem (idempotent; not a stream op)
    cudaFuncSetAttribute(gemm_tf32<0>, cudaFuncAttributeMaxDynamicSharedMemorySize, SMEM_BYTES);
    cudaFuncSetAttribute(gemm_tf32<1>, cudaFuncAttributeMaxDynamicSharedMemorySize, SMEM_BYTES);
    cudaFuncSetAttribute(gemm_tf32<2>, cudaFuncAttributeMaxDynamicSharedMemorySize, SMEM_BYTES);
    cudaFuncSetAttribute(gemm_tf32<3>, cudaFuncAttributeMaxDynamicSharedMemorySize, SMEM_BYTES);

    // router + deterministic bucketing
    router_kernel<<<T_, 256>>>(x, gw, sg);
    count_scan_kernel<<<1, 256>>>();
    bucket_kernel<<<E_, 32>>>();

    // routed experts (grouped, gathered rows)
    gemm_tf32<2><<<dim3(2 * I_ / BN, T_ / BM, E_), 128, SMEM_BYTES>>>(x, wgu, nullptr);
    silu_mul_kernel<<<(T_ * TK_ * I_ / 4 + 255) / 256, 256>>>(T_ * TK_, I_);
    gemm_tf32<3><<<dim3(H_ / BN, T_ / BM, E_), 128, SMEM_BYTES>>>(nullptr, wd, nullptr);

    // shared expert (dense) -> writes out = shared (sigmoid-gated)
    gemm_tf32<0><<<dim3(2 * IS_ / BN, T_ / BM, 1), 128, SMEM_BYTES>>>(x, sgu, nullptr);
    silu_mul_kernel<<<(T_ * IS_ / 4 + 255) / 256, 256>>>(T_, IS_);
    gemm_tf32<1><<<dim3(H_ / BN, T_ / BM, 1), 128, SMEM_BYTES>>>(nullptr, sd, out);

    // out += routed combine
    reduce_kernel<<<T_ * H_ / 4 / 256, 256>>>(out);
}

// round 14
// speedup vs baseline: 1.1706x; 1.1626x over previous
#include <cuda_runtime.h>
#include <cuda_fp16.h>
#include <cstdint>
#include <math.h>

// ---------------- problem dims (Qwen3-Omni Talker SparseMoeBlock) ------------
#define T_  2048   // tokens
#define H_  2048   // hidden
#define I_  1408   // routed intermediate
#define IS_ 5632   // shared intermediate
#define E_  32     // experts
#define TK_ 4      // top-k

// ---------------- static scratch (no allocations allowed) --------------------
__device__ __align__(16) float  g_act[23068672];  // max(8192*2816, 2048*11264)
__device__ __align__(16) __half g_hh[11534336];   // max(8192*1408, 2048*5632), fp16
__device__ __align__(16) float  g_y[16777216];    // 8192 * 2048 pair outputs

__device__ int   g_topk_idx[T_ * TK_];
__device__ float g_topk_w[T_ * TK_];
__device__ float g_sgate[T_];
__device__ int   g_cnt[E_];
__device__ int   g_off[E_ + 1];
__device__ int   g_pair_token[T_ * TK_];
__device__ float g_pair_w[T_ * TK_];
__device__ int   g_slot[T_ * TK_];

// ---------------- router: logits -> softmax top4 -> renorm + sigmoid gate ----
__global__ void router_kernel(const float* __restrict__ x,
                              const float* __restrict__ gate_w,
                              const float* __restrict__ sgate_w) {
    const int t = blockIdx.x;
    const float* xr = x + (size_t)t * H_;
    __shared__ float xs[H_];
    __shared__ float logits[E_];
    __shared__ float red[256];
    const int tid = threadIdx.x;

    for (int i = tid * 4; i < H_; i += 256 * 4) {
        *(float4*)(xs + i) = *(const float4*)(xr + i);
    }
    __syncthreads();

    const int wid = tid >> 5, lane = tid & 31;
    const int ebase = wid * 4;
    float a0 = 0.f, a1 = 0.f, a2 = 0.f, a3 = 0.f;
    for (int h = lane; h < H_; h += 32) {
        const float xv = xs[h];
        const float* gw = gate_w + (size_t)h * E_ + ebase;
        a0 += xv * gw[0]; a1 += xv * gw[1];
        a2 += xv * gw[2]; a3 += xv * gw[3];
    }
    #pragma unroll
    for (int o = 16; o; o >>= 1) {
        a0 += __shfl_xor_sync(~0u, a0, o);
        a1 += __shfl_xor_sync(~0u, a1, o);
        a2 += __shfl_xor_sync(~0u, a2, o);
        a3 += __shfl_xor_sync(~0u, a3, o);
    }
    if (lane == 0) {
        logits[ebase + 0] = a0; logits[ebase + 1] = a1;
        logits[ebase + 2] = a2; logits[ebase + 3] = a3;
    }

    float p = 0.f;
    for (int h = tid; h < H_; h += 256) p += xs[h] * sgate_w[h];
    red[tid] = p;
    __syncthreads();
    #pragma unroll
    for (int s = 128; s; s >>= 1) {
        if (tid < s) red[tid] += red[tid + s];
        __syncthreads();
    }

    if (tid == 0) {
        g_sgate[t] = 1.f / (1.f + expf(-red[0]));
        float l[E_];
        #pragma unroll
        for (int e = 0; e < E_; e++) l[e] = logits[e];
        int   idx[TK_];
        float val[TK_];
        #pragma unroll
        for (int k = 0; k < TK_; k++) {
            int bi = 0; float bv = -1e30f;
            for (int e = 0; e < E_; e++)
                if (l[e] > bv) { bv = l[e]; bi = e; }
            idx[k] = bi; val[k] = bv; l[bi] = -1e30f;
        }
        const float mx = val[0];
        float s = 0.f, w[TK_];
        #pragma unroll
        for (int k = 0; k < TK_; k++) { w[k] = expf(val[k] - mx); s += w[k]; }
        const float inv = 1.f / s;
        #pragma unroll
        for (int k = 0; k < TK_; k++) {
            g_topk_idx[t * TK_ + k] = idx[k];
            g_topk_w[t * TK_ + k]   = w[k] * inv;
        }
    }
}

// ---------------- per-expert counts + exclusive scan (1 block) ---------------
__global__ void count_scan_kernel() {
    __shared__ int sc[E_];
    const int tid = threadIdx.x;
    if (tid < E_) sc[tid] = 0;
    __syncthreads();
    for (int i = tid; i < T_ * TK_; i += 256)
        atomicAdd(&sc[g_topk_idx[i]], 1);
    __syncthreads();
    if (tid == 0) {
        int run = 0;
        for (int e = 0; e < E_; e++) {
            g_off[e] = run;
            g_cnt[e] = sc[e];
            run += sc[e];
        }
        g_off[E_] = run;
    }
}

// ---------------- deterministic bucketing: 1 warp per expert -----------------
__global__ void bucket_kernel() {
    const int e = blockIdx.x;
    const int lane = threadIdx.x;
    const int base = g_off[e];
    int cnt = 0;
    for (int t0 = 0; t0 < T_; t0 += 32) {
        const int t = t0 + lane;
        int km = -1; float w = 0.f;
        #pragma unroll
        for (int k = 0; k < TK_; k++)
            if (g_topk_idx[t * TK_ + k] == e) { km = k; w = g_topk_w[t * TK_ + k]; }
        const unsigned mask = __ballot_sync(~0u, km >= 0);
        if (km >= 0) {
            const int p = base + cnt + __popc(mask & ((1u << lane) - 1));
            g_pair_token[p] = t;
            g_pair_w[p]     = w;
            g_slot[t * TK_ + km] = p;
        }
        cnt += __popc(mask);
    }
}

// ================= fp16 HMMA GEMM (ldmatrix + m16n8k16) ======================
#define BM 128
#define BN 128
#define BK 32
#define SA 40     // A smem stride in halfs (80B rows: conflict-free, r*5 mod 8)
#define SB 136    // B smem stride in halfs (272B rows: conflict-free, k*17 mod 8)

__device__ __forceinline__ uint32_t pk2h(float a, float b) {
    __half2 h = __floats2half2_rn(a, b);   // a -> low, b -> high
    return *reinterpret_cast<uint32_t*>(&h);
}
__device__ __forceinline__ void ldm_x4(uint32_t* r, uint32_t addr) {
    asm volatile("ldmatrix.sync.aligned.m8n8.x4.shared.b16 {%0,%1,%2,%3}, [%4];"
                 : "=r"(r[0]), "=r"(r[1]), "=r"(r[2]), "=r"(r[3]) : "r"(addr));
}
__device__ __forceinline__ void ldm_x4_t(uint32_t* r, uint32_t addr) {
    asm volatile("ldmatrix.sync.aligned.m8n8.x4.trans.shared.b16 {%0,%1,%2,%3}, [%4];"
                 : "=r"(r[0]), "=r"(r[1]), "=r"(r[2]), "=r"(r[3]) : "r"(addr));
}
__device__ __forceinline__ void mma_f16(float* c, const uint32_t* a, const uint32_t* b) {
    asm volatile(
        "mma.sync.aligned.m16n8k16.row.col.f32.f16.f16.f32 "
        "{%0,%1,%2,%3}, {%4,%5,%6,%7}, {%8,%9}, {%0,%1,%2,%3};"
        : "+f"(c[0]), "+f"(c[1]), "+f"(c[2]), "+f"(c[3])
        : "r"(a[0]), "r"(a[1]), "r"(a[2]), "r"(a[3]), "r"(b[0]), "r"(b[1]));
}

// MODE 0: shared GEMM1   act[T,2IS]   = x @ shared_gate_up
// MODE 1: shared GEMM2   out[T,H]     = (hh @ shared_down) * sgate[t]
// MODE 2: routed GEMM1   act[p,2I]    = gather(x) @ w_gate_up[e]   (grouped)
// MODE 3: routed GEMM2   y[p,H]       = (hh @ w_down[e]) * pair_w[p](grouped)
template<int MODE>
__global__ void __launch_bounds__(256)
gemm_hmma(const float* __restrict__ Aarg, const float* __restrict__ Barg,
          float* __restrict__ Carg)
{
    constexpr int N  = (MODE == 0) ? 2 * IS_ : (MODE == 2) ? 2 * I_ : H_;
    constexpr int Kd = (MODE == 0) ? H_ : (MODE == 1) ? IS_ : (MODE == 2) ? H_ : I_;
    constexpr int nK = Kd / BK;
    constexpr bool AHALF = (MODE == 1 || MODE == 3);

    float* Cb = (MODE == 1) ? Carg
              : (MODE == 3) ? (float*)g_y
                            : (float*)g_act;

    const int tid  = threadIdx.x;
    const int wid  = tid >> 5;
    const int lane = tid & 31;
    const int m0 = blockIdx.x * BM;   // m fastest: consecutive CTAs share B in L2
    const int n0 = blockIdx.y * BN;
    int Mcnt = T_, rowoff = 0;
    const float* B = Barg;
    if (MODE >= 2) {
        const int e = blockIdx.z;
        Mcnt = g_cnt[e];
        if (m0 >= Mcnt) return;       // early-exit empty tiles
        rowoff = g_off[e];
        B = Barg + (size_t)e * ((size_t)Kd * N);
    }

    __shared__ __align__(16) __half sA[2][BM * SA];   // 2 x 10240 B
    __shared__ __align__(16) __half sB[2][BK * SB];   // 2 x  8704 B

    // ---- staging assignments ----
    const int arow = tid & 127;            // A: row within tile
    const int kh   = (tid >> 7) << 4;      // A: k-half offset (0 or 16 halfs)
    const int bk   = tid >> 3;             // B: k row (0..31)
    const int bn16 = (tid & 7) << 4;       // B: n offset (16-half chunks)

    const float*  aF = nullptr;
    const __half* aH = nullptr;
    {
        int lr = m0 + arow;
        if (lr >= Mcnt) lr = Mcnt - 1;     // safe duplicate; masked in epilogue
        int grow;
        if (MODE == 2)      grow = g_pair_token[rowoff + lr];
        else if (MODE == 3) grow = rowoff + lr;
        else                grow = lr;
        if (AHALF) aH = g_hh + (size_t)grow * Kd + kh;
        else       aF = Aarg + (size_t)grow * Kd + kh;
    }
    const float* bSrc = B + (size_t)bk * N + n0 + bn16;

    uint4 aS0, aS1, bS0, bS1;
    auto gload = [&](int kt) {
        if (AHALF) {
            const uint4* s = (const uint4*)(aH + kt * BK);
            aS0 = s[0]; aS1 = s[1];
        } else {
            const float4* s = (const float4*)(aF + kt * BK);
            float4 f0 = s[0], f1 = s[1], f2 = s[2], f3 = s[3];
            aS0 = make_uint4(pk2h(f0.x,f0.y), pk2h(f0.z,f0.w), pk2h(f1.x,f1.y), pk2h(f1.z,f1.w));
            aS1 = make_uint4(pk2h(f2.x,f2.y), pk2h(f2.z,f2.w), pk2h(f3.x,f3.y), pk2h(f3.z,f3.w));
        }
        const float4* s = (const float4*)(bSrc + (size_t)kt * BK * N);
        float4 f0 = s[0], f1 = s[1], f2 = s[2], f3 = s[3];
        bS0 = make_uint4(pk2h(f0.x,f0.y), pk2h(f0.z,f0.w), pk2h(f1.x,f1.y), pk2h(f1.z,f1.w));
        bS1 = make_uint4(pk2h(f2.x,f2.y), pk2h(f2.z,f2.w), pk2h(f3.x,f3.y), pk2h(f3.z,f3.w));
    };
    auto sts = [&](int buf) {
        uint4* ad = (uint4*)(&sA[buf][arow * SA + kh]);
        ad[0] = aS0; ad[1] = aS1;
        uint4* bd = (uint4*)(&sB[buf][bk * SB + bn16]);
        bd[0] = bS0; bd[1] = bS1;
    };

    // ---- per-warp mma geometry ----
    const int wm = (wid & 1) * 64;    // 2 warps along M
    const int wn = (wid >> 1) * 32;   // 4 warps along N
    const int q  = lane >> 3;
    const int r7 = lane & 7;
    const int lrow = (q & 1) * 8 + r7;   // ldmatrix lane row
    const int lcol = (q >> 1) * 8;       // ldmatrix lane col (halfs)

    float acc[4][4][4];
    #pragma unroll
    for (int i = 0; i < 4; i++)
        #pragma unroll
        for (int j = 0; j < 4; j++)
            #pragma unroll
            for (int c = 0; c < 4; c++) acc[i][j][c] = 0.f;

    const uint32_t saAddr = (uint32_t)__cvta_generic_to_shared(&sA[0][0]);
    const uint32_t sbAddr = (uint32_t)__cvta_generic_to_shared(&sB[0][0]);
    constexpr uint32_t ABUFB = BM * SA * 2;   // bytes per A buffer
    constexpr uint32_t BBUFB = BK * SB * 2;   // bytes per B buffer

    auto compute = [&](int buf) {
        const uint32_t aB = saAddr + buf * ABUFB;
        const uint32_t bB = sbAddr + buf * BBUFB;
        #pragma unroll
        for (int ks = 0; ks < 2; ks++) {
            uint32_t af[4][4], bf[2][4];
            #pragma unroll
            for (int mt = 0; mt < 4; mt++)
                ldm_x4(af[mt], aB + ((wm + mt * 16 + lrow) * SA + ks * 16 + lcol) * 2);
            #pragma unroll
            for (int p = 0; p < 2; p++)
                ldm_x4_t(bf[p], bB + ((ks * 16 + lrow) * SB + wn + p * 16 + lcol) * 2);
            #pragma unroll
            for (int mt = 0; mt < 4; mt++)
                #pragma unroll
                for (int nt = 0; nt < 4; nt++)
                    mma_f16(acc[mt][nt], af[mt], &bf[nt >> 1][(nt & 1) * 2]);
        }
    };

    // ---- register-pipelined double-buffered mainloop ----
    gload(0);
    sts(0);
    __syncthreads();
    for (int kt = 0; kt < nK; kt++) {
        const int buf = kt & 1;
        if (kt + 1 < nK) gload(kt + 1);
        compute(buf);
        if (kt + 1 < nK) sts(buf ^ 1);
        __syncthreads();
    }

    // ---- epilogue: per-row scale, guarded rows, float2 stores ----
    const int fr = lane >> 2;
    const int fc = lane & 3;
    #pragma unroll
    for (int mt = 0; mt < 4; mt++) {
        #pragma unroll
        for (int half = 0; half < 2; half++) {
            const int rloc = wm + mt * 16 + fr + half * 8;
            const int lr = m0 + rloc;
            if (lr >= Mcnt) continue;
            float s = 1.f;
            size_t crow = (size_t)lr;
            if (MODE == 1) s = g_sgate[lr];
            if (MODE == 2) crow = (size_t)(rowoff + lr);
            if (MODE == 3) { crow = (size_t)(rowoff + lr); s = g_pair_w[rowoff + lr]; }
            float* Crow = Cb + crow * N + n0;
            #pragma unroll
            for (int nt = 0; nt < 4; nt++) {
                const int cc = wn + nt * 8 + fc * 2;
                float2 v;
                v.x = acc[mt][nt][half * 2 + 0] * s;
                v.y = acc[mt][nt][half * 2 + 1] * s;
                *(float2*)(Crow + cc) = v;
            }
        }
    }
}

// ---------------- SiLU(gate) * up: g_act -> g_hh (fp16) ------------------------
__global__ void silu_mul_kernel(int rows, int inter) {
    const long long n4 = (long long)rows * inter / 4;
    const long long i = (long long)blockIdx.x * blockDim.x + threadIdx.x;
    if (i >= n4) return;
    const long long el = i * 4;
    const int row = (int)(el / inter);
    const int col = (int)(el % inter);
    const float* a = g_act + (size_t)row * (2 * (size_t)inter);
    const float4 g = *(const float4*)(a + col);
    const float4 u = *(const float4*)(a + inter + col);
    float ox = g.x / (1.f + expf(-g.x)) * u.x;
    float oy = g.y / (1.f + expf(-g.y)) * u.y;
    float oz = g.z / (1.f + expf(-g.z)) * u.z;
    float ow = g.w / (1.f + expf(-g.w)) * u.w;
    __half2 h0 = __floats2half2_rn(ox, oy);
    __half2 h1 = __floats2half2_rn(oz, ow);
    uint2 o = make_uint2(*reinterpret_cast<uint32_t*>(&h0),
                         *reinterpret_cast<uint32_t*>(&h1));
    *(uint2*)(g_hh + (size_t)row * inter + col) = o;
}

// ---------------- final combine: out += sum_k y[slot[t][k]] --------------------
__global__ void reduce_kernel(float* __restrict__ out) {
    const int i = blockIdx.x * blockDim.x + threadIdx.x;  // over T*H/4
    const int t = i / (H_ / 4);
    const int c = (i % (H_ / 4)) * 4;
    const int* sl = g_slot + t * TK_;
    float* op = out + (size_t)t * H_ + c;
    float4 a = *(float4*)op;
    #pragma unroll
    for (int k = 0; k < TK_; k++) {
        const float4 y = *(const float4*)(g_y + (size_t)sl[k] * H_ + c);
        a.x += y.x; a.y += y.y; a.z += y.z; a.w += y.w;
    }
    *(float4*)op = a;
}

// ---------------- launch ------------------------------------------------------
extern "C" void kernel_launch(void* const* d_in, const int* in_sizes, int n_in,
                              void* d_out, int out_size) {
    const float* x   = (const float*)d_in[0];
    const float* gw  = (const float*)d_in[1];
    const float* wgu = (const float*)d_in[2];
    const float* wd  = (const float*)d_in[3];
    const float* sgu = (const float*)d_in[4];
    const float* sd  = (const float*)d_in[5];
    const float* sg  = (const float*)d_in[6];
    float* out = (float*)d_out;
    (void)in_sizes; (void)n_in; (void)out_size;

    // router + deterministic bucketing
    router_kernel<<<T_, 256>>>(x, gw, sg);
    count_scan_kernel<<<1, 256>>>();
    bucket_kernel<<<E_, 32>>>();

    // routed experts (grouped, gathered rows)  [grid: m fastest for B reuse]
    gemm_hmma<2><<<dim3(T_ / BM, 2 * I_ / BN, E_), 256>>>(x, wgu, nullptr);
    silu_mul_kernel<<<(T_ * TK_ * I_ / 4 + 255) / 256, 256>>>(T_ * TK_, I_);
    gemm_hmma<3><<<dim3(T_ / BM, H_ / BN, E_), 256>>>(nullptr, wd, nullptr);

    // shared expert (dense) -> writes out = shared (sigmoid-gated)
    gemm_hmma<0><<<dim3(T_ / BM, 2 * IS_ / BN, 1), 256>>>(x, sgu, nullptr);
    silu_mul_kernel<<<(T_ * IS_ / 4 + 255) / 256, 256>>>(T_, IS_);
    gemm_hmma<1><<<dim3(T_ / BM, H_ / BN, 1), 256>>>(nullptr, sd, out);

    // out += routed combine
    reduce_kernel<<<T_ * H_ / 4 / 256, 256>>>(out);
}

// round 16
// speedup vs baseline: 1.5950x; 1.3625x over previous
#include <cuda_runtime.h>
#include <cuda_fp16.h>
#include <cstdint>
#include <math.h>

// ---------------- problem dims (Qwen3-Omni Talker SparseMoeBlock) ------------
#define T_  2048   // tokens
#define H_  2048   // hidden
#define I_  1408   // routed intermediate
#define IS_ 5632   // shared intermediate
#define E_  32     // experts
#define TK_ 4      // top-k

// ---------------- static scratch (no allocations allowed) --------------------
__device__ __align__(16) float  g_act[23068672];  // max(8192*2816, 2048*11264)
__device__ __align__(16) __half g_hh[11534336];   // silu output, fp16
__device__ __align__(16) float  g_y[16777216];    // 8192 * 2048 pair outputs

// fp16 pre-converted operands
__device__ __align__(16) __half g_xh[4194304];      // x          [T,H]
__device__ __align__(16) __half g_wguh[184549376];  // w_gate_up  [E,H,2I]
__device__ __align__(16) __half g_wdh[92274688];    // w_down     [E,I,H]
__device__ __align__(16) __half g_sguh[23068672];   // shared_gu  [H,2IS]
__device__ __align__(16) __half g_sdh[11534336];    // shared_dn  [IS,H]

__device__ int   g_topk_idx[T_ * TK_];
__device__ float g_topk_w[T_ * TK_];
__device__ float g_sgate[T_];
__device__ int   g_cnt[E_];
__device__ int   g_off[E_ + 1];
__device__ int   g_pair_token[T_ * TK_];
__device__ float g_pair_w[T_ * TK_];
__device__ int   g_slot[T_ * TK_];

// ---------------- f32 -> f16 bulk convert -------------------------------------
__global__ void f2h_kernel(const float* __restrict__ src, __half* __restrict__ dst,
                           long long n8) {
    const long long i = (long long)blockIdx.x * blockDim.x + threadIdx.x;
    if (i >= n8) return;
    const float4 a = *(const float4*)(src + i * 8);
    const float4 b = *(const float4*)(src + i * 8 + 4);
    __half2 h0 = __floats2half2_rn(a.x, a.y);
    __half2 h1 = __floats2half2_rn(a.z, a.w);
    __half2 h2 = __floats2half2_rn(b.x, b.y);
    __half2 h3 = __floats2half2_rn(b.z, b.w);
    uint4 o;
    o.x = *reinterpret_cast<uint32_t*>(&h0);
    o.y = *reinterpret_cast<uint32_t*>(&h1);
    o.z = *reinterpret_cast<uint32_t*>(&h2);
    o.w = *reinterpret_cast<uint32_t*>(&h3);
    *(uint4*)(dst + i * 8) = o;
}

// ---------------- router: logits -> softmax top4 -> renorm + sigmoid gate ----
__global__ void router_kernel(const float* __restrict__ x,
                              const float* __restrict__ gate_w,
                              const float* __restrict__ sgate_w) {
    const int t = blockIdx.x;
    const float* xr = x + (size_t)t * H_;
    __shared__ float xs[H_];
    __shared__ float logits[E_];
    __shared__ float red[256];
    const int tid = threadIdx.x;

    for (int i = tid * 4; i < H_; i += 256 * 4) {
        *(float4*)(xs + i) = *(const float4*)(xr + i);
    }
    __syncthreads();

    const int wid = tid >> 5, lane = tid & 31;
    const int ebase = wid * 4;
    float a0 = 0.f, a1 = 0.f, a2 = 0.f, a3 = 0.f;
    for (int h = lane; h < H_; h += 32) {
        const float xv = xs[h];
        const float* gw = gate_w + (size_t)h * E_ + ebase;
        a0 += xv * gw[0]; a1 += xv * gw[1];
        a2 += xv * gw[2]; a3 += xv * gw[3];
    }
    #pragma unroll
    for (int o = 16; o; o >>= 1) {
        a0 += __shfl_xor_sync(~0u, a0, o);
        a1 += __shfl_xor_sync(~0u, a1, o);
        a2 += __shfl_xor_sync(~0u, a2, o);
        a3 += __shfl_xor_sync(~0u, a3, o);
    }
    if (lane == 0) {
        logits[ebase + 0] = a0; logits[ebase + 1] = a1;
        logits[ebase + 2] = a2; logits[ebase + 3] = a3;
    }

    float p = 0.f;
    for (int h = tid; h < H_; h += 256) p += xs[h] * sgate_w[h];
    red[tid] = p;
    __syncthreads();
    #pragma unroll
    for (int s = 128; s; s >>= 1) {
        if (tid < s) red[tid] += red[tid + s];
        __syncthreads();
    }

    if (tid == 0) {
        g_sgate[t] = 1.f / (1.f + expf(-red[0]));
        float l[E_];
        #pragma unroll
        for (int e = 0; e < E_; e++) l[e] = logits[e];
        int   idx[TK_];
        float val[TK_];
        #pragma unroll
        for (int k = 0; k < TK_; k++) {
            int bi = 0; float bv = -1e30f;
            for (int e = 0; e < E_; e++)
                if (l[e] > bv) { bv = l[e]; bi = e; }
            idx[k] = bi; val[k] = bv; l[bi] = -1e30f;
        }
        const float mx = val[0];
        float s = 0.f, w[TK_];
        #pragma unroll
        for (int k = 0; k < TK_; k++) { w[k] = expf(val[k] - mx); s += w[k]; }
        const float inv = 1.f / s;
        #pragma unroll
        for (int k = 0; k < TK_; k++) {
            g_topk_idx[t * TK_ + k] = idx[k];
            g_topk_w[t * TK_ + k]   = w[k] * inv;
        }
    }
}

// ---------------- per-expert counts + exclusive scan (1 block) ---------------
__global__ void count_scan_kernel() {
    __shared__ int sc[E_];
    const int tid = threadIdx.x;
    if (tid < E_) sc[tid] = 0;
    __syncthreads();
    for (int i = tid; i < T_ * TK_; i += 256)
        atomicAdd(&sc[g_topk_idx[i]], 1);
    __syncthreads();
    if (tid == 0) {
        int run = 0;
        for (int e = 0; e < E_; e++) {
            g_off[e] = run;
            g_cnt[e] = sc[e];
            run += sc[e];
        }
        g_off[E_] = run;
    }
}

// ---------------- deterministic bucketing: 1 warp per expert -----------------
__global__ void bucket_kernel() {
    const int e = blockIdx.x;
    const int lane = threadIdx.x;
    const int base = g_off[e];
    int cnt = 0;
    for (int t0 = 0; t0 < T_; t0 += 32) {
        const int t = t0 + lane;
        int km = -1; float w = 0.f;
        #pragma unroll
        for (int k = 0; k < TK_; k++)
            if (g_topk_idx[t * TK_ + k] == e) { km = k; w = g_topk_w[t * TK_ + k]; }
        const unsigned mask = __ballot_sync(~0u, km >= 0);
        if (km >= 0) {
            const int p = base + cnt + __popc(mask & ((1u << lane) - 1));
            g_pair_token[p] = t;
            g_pair_w[p]     = w;
            g_slot[t * TK_ + km] = p;
        }
        cnt += __popc(mask);
    }
}

// ================= fp16 HMMA GEMM: cp.async + ldmatrix + m16n8k16 ============
#define BM 128
#define BN 256
#define BK 32
#define SAH 40    // A smem row stride in halfs (80B: conflict-free ldmatrix)
#define SBH 264   // B smem row stride in halfs (528B: conflict-free ldmatrix)
#define ABUFB (BM * SAH * 2)            // 10240 B
#define BBUFB (BK * SBH * 2)            // 16896 B
#define STAGEB (ABUFB + BBUFB)          // 27136 B
#define SMEM_BYTES (2 * STAGEB)         // 54272 B

__device__ __forceinline__ void ldm_x4(uint32_t* r, uint32_t addr) {
    asm volatile("ldmatrix.sync.aligned.m8n8.x4.shared.b16 {%0,%1,%2,%3}, [%4];"
                 : "=r"(r[0]), "=r"(r[1]), "=r"(r[2]), "=r"(r[3]) : "r"(addr));
}
__device__ __forceinline__ void ldm_x4_t(uint32_t* r, uint32_t addr) {
    asm volatile("ldmatrix.sync.aligned.m8n8.x4.trans.shared.b16 {%0,%1,%2,%3}, [%4];"
                 : "=r"(r[0]), "=r"(r[1]), "=r"(r[2]), "=r"(r[3]) : "r"(addr));
}
__device__ __forceinline__ void mma_f16(float* c, const uint32_t* a, const uint32_t* b) {
    asm volatile(
        "mma.sync.aligned.m16n8k16.row.col.f32.f16.f16.f32 "
        "{%0,%1,%2,%3}, {%4,%5,%6,%7}, {%8,%9}, {%0,%1,%2,%3};"
        : "+f"(c[0]), "+f"(c[1]), "+f"(c[2]), "+f"(c[3])
        : "r"(a[0]), "r"(a[1]), "r"(a[2]), "r"(a[3]), "r"(b[0]), "r"(b[1]));
}
__device__ __forceinline__ void cp16(uint32_t dst, const void* src) {
    asm volatile("cp.async.cg.shared.global [%0], [%1], 16;" :: "r"(dst), "l"(src));
}

// MODE 0: shared GEMM1   act[T,2IS]   = xh @ shared_gate_up
// MODE 1: shared GEMM2   out[T,H]     = (hh @ shared_down) * sgate[t]
// MODE 2: routed GEMM1   act[p,2I]    = gather(xh) @ w_gate_up[e]  (grouped)
// MODE 3: routed GEMM2   y[p,H]       = (hh @ w_down[e]) * pair_w[p] (grouped)
template<int MODE>
__global__ void __launch_bounds__(256)
gemm_cp(const __half* __restrict__ Bh, float* __restrict__ Carg)
{
    constexpr int N  = (MODE == 0) ? 2 * IS_ : (MODE == 2) ? 2 * I_ : H_;
    constexpr int Kd = (MODE == 0) ? H_ : (MODE == 1) ? IS_ : (MODE == 2) ? H_ : I_;
    constexpr int nK = Kd / BK;

    const __half* Ab = (MODE == 1 || MODE == 3) ? (const __half*)g_hh
                                                 : (const __half*)g_xh;
    float* Cb = (MODE == 1) ? Carg
              : (MODE == 3) ? (float*)g_y
                            : (float*)g_act;

    const int tid  = threadIdx.x;
    const int wid  = tid >> 5;
    const int lane = tid & 31;
    const int m0 = blockIdx.x * BM;   // m fastest: consecutive CTAs share B in L2
    const int n0 = blockIdx.y * BN;
    int Mcnt = T_, rowoff = 0;
    const __half* B = Bh;
    if (MODE >= 2) {
        const int e = blockIdx.z;
        Mcnt = g_cnt[e];
        if (m0 >= Mcnt) return;       // early-exit empty tiles
        rowoff = g_off[e];
        B = Bh + (size_t)e * ((size_t)Kd * N);
    }

    extern __shared__ __half smh[];
    const uint32_t sbase = (uint32_t)__cvta_generic_to_shared(smh);

    // ---- staging assignments ----
    // A: 128 rows x 64B; thread = (row = tid&127, 32B half of row = tid>>7)
    const int arow = tid & 127;
    const int ack  = tid >> 7;
    const __half* aSrc;
    {
        int lr = m0 + arow;
        if (lr >= Mcnt) lr = Mcnt - 1;     // safe duplicate; masked in epilogue
        int grow;
        if (MODE == 2)      grow = g_pair_token[rowoff + lr];
        else if (MODE == 3) grow = rowoff + lr;
        else                grow = lr;
        aSrc = Ab + (size_t)grow * Kd + ack * 16;
    }
    const uint32_t aDst = sbase + arow * (SAH * 2) + ack * 32;
    // B: 32 rows x 512B; row = tid>>3, chunk lane = tid&7.
    // Thread covers 16B chunks c = bg + 8i (i=0..3): col = bg*8 + i*64 halfs.
    const int bk  = tid >> 3;
    const int bg  = tid & 7;
    const __half* bSrc = B + (size_t)bk * N + n0 + bg * 8;
    const uint32_t bDst = sbase + ABUFB + bk * (SBH * 2) + bg * 16;

    auto stage = [&](int kt, int buf) {
        const uint32_t so = buf * STAGEB;
        const __half* as = aSrc + kt * BK;
        cp16(aDst + so,      as);
        cp16(aDst + so + 16, as + 8);
        const __half* bs = bSrc + (size_t)kt * BK * N;
        #pragma unroll
        for (int i = 0; i < 4; i++)
            cp16(bDst + so + i * 128, bs + i * 64);
        asm volatile("cp.async.commit_group;");
    };

    // ---- per-warp mma geometry: 2(M) x 4(N) warps, 64x64 tiles ----
    const int wm = (wid & 1) * 64;
    const int wn = (wid >> 1) * 64;
    const int q  = lane >> 3;
    const int r7 = lane & 7;
    const int lrow = (q & 1) * 8 + r7;
    const int lcol = (q >> 1) * 8;

    float acc[4][8][4];
    #pragma unroll
    for (int i = 0; i < 4; i++)
        #pragma unroll
        for (int j = 0; j < 8; j++)
            #pragma unroll
            for (int c = 0; c < 4; c++) acc[i][j][c] = 0.f;

    auto compute = [&](int buf) {
        const uint32_t aB = sbase + buf * STAGEB;
        const uint32_t bB = aB + ABUFB;
        #pragma unroll
        for (int ks = 0; ks < 2; ks++) {
            uint32_t af[4][4], bf[4][4];
            #pragma unroll
            for (int mt = 0; mt < 4; mt++)
                ldm_x4(af[mt], aB + ((wm + mt * 16 + lrow) * SAH + ks * 16 + lcol) * 2);
            #pragma unroll
            for (int p = 0; p < 4; p++)
                ldm_x4_t(bf[p], bB + ((ks * 16 + lrow) * SBH + wn + p * 16 + lcol) * 2);
            #pragma unroll
            for (int mt = 0; mt < 4; mt++)
                #pragma unroll
                for (int nt = 0; nt < 8; nt++)
                    mma_f16(acc[mt][nt], af[mt], &bf[nt >> 1][(nt & 1) * 2]);
        }
    };

    // ---- cp.async double-buffered mainloop ----
    stage(0, 0);
    for (int kt = 0; kt < nK; kt++) {
        const int buf = kt & 1;
        if (kt + 1 < nK) {
            stage(kt + 1, buf ^ 1);
            asm volatile("cp.async.wait_group 1;");
        } else {
            asm volatile("cp.async.wait_group 0;");
        }
        __syncthreads();
        compute(buf);
        __syncthreads();   // protect buf before stage(kt+2) overwrites it
    }

    // ---- epilogue: per-row scale, guarded rows, float2 stores ----
    const int fr = lane >> 2;
    const int fc = lane & 3;
    #pragma unroll
    for (int mt = 0; mt < 4; mt++) {
        #pragma unroll
        for (int half = 0; half < 2; half++) {
            const int rloc = wm + mt * 16 + fr + half * 8;
            const int lr = m0 + rloc;
            if (lr >= Mcnt) continue;
            float s = 1.f;
            size_t crow = (size_t)lr;
            if (MODE == 1) s = g_sgate[lr];
            if (MODE == 2) crow = (size_t)(rowoff + lr);
            if (MODE == 3) { crow = (size_t)(rowoff + lr); s = g_pair_w[rowoff + lr]; }
            float* Crow = Cb + crow * N + n0;
            #pragma unroll
            for (int nt = 0; nt < 8; nt++) {
                const int cc = wn + nt * 8 + fc * 2;
                float2 v;
                v.x = acc[mt][nt][half * 2 + 0] * s;
                v.y = acc[mt][nt][half * 2 + 1] * s;
                *(float2*)(Crow + cc) = v;
            }
        }
    }
}

// ---------------- SiLU(gate) * up: g_act -> g_hh (fp16) ------------------------
__global__ void silu_mul_kernel(int rows, int inter) {
    const long long n4 = (long long)rows * inter / 4;
    const long long i = (long long)blockIdx.x * blockDim.x + threadIdx.x;
    if (i >= n4) return;
    const long long el = i * 4;
    const int row = (int)(el / inter);
    const int col = (int)(el % inter);
    const float* a = g_act + (size_t)row * (2 * (size_t)inter);
    const float4 g = *(const float4*)(a + col);
    const float4 u = *(const float4*)(a + inter + col);
    float ox = g.x / (1.f + expf(-g.x)) * u.x;
    float oy = g.y / (1.f + expf(-g.y)) * u.y;
    float oz = g.z / (1.f + expf(-g.z)) * u.z;
    float ow = g.w / (1.f + expf(-g.w)) * u.w;
    __half2 h0 = __floats2half2_rn(ox, oy);
    __half2 h1 = __floats2half2_rn(oz, ow);
    uint2 o = make_uint2(*reinterpret_cast<uint32_t*>(&h0),
                         *reinterpret_cast<uint32_t*>(&h1));
    *(uint2*)(g_hh + (size_t)row * inter + col) = o;
}

// ---------------- final combine: out += sum_k y[slot[t][k]] --------------------
__global__ void reduce_kernel(float* __restrict__ out) {
    const int i = blockIdx.x * blockDim.x + threadIdx.x;  // over T*H/4
    const int t = i / (H_ / 4);
    const int c = (i % (H_ / 4)) * 4;
    const int* sl = g_slot + t * TK_;
    float* op = out + (size_t)t * H_ + c;
    float4 a = *(float4*)op;
    #pragma unroll
    for (int k = 0; k < TK_; k++) {
        const float4 y = *(const float4*)(g_y + (size_t)sl[k] * H_ + c);
        a.x += y.x; a.y += y.y; a.z += y.z; a.w += y.w;
    }
    *(float4*)op = a;
}

// ---------------- launch ------------------------------------------------------
extern "C" void kernel_launch(void* const* d_in, const int* in_sizes, int n_in,
                              void* d_out, int out_size) {
    const float* x   = (const float*)d_in[0];
    const float* gw  = (const float*)d_in[1];
    const float* wgu = (const float*)d_in[2];
    const float* wd  = (const float*)d_in[3];
    const float* sgu = (const float*)d_in[4];
    const float* sd  = (const float*)d_in[5];
    const float* sg  = (const float*)d_in[6];
    float* out = (float*)d_out;
    (void)in_sizes; (void)n_in; (void)out_size;

    cudaFuncSetAttribute(gemm_cp<0>, cudaFuncAttributeMaxDynamicSharedMemorySize, SMEM_BYTES);
    cudaFuncSetAttribute(gemm_cp<1>, cudaFuncAttributeMaxDynamicSharedMemorySize, SMEM_BYTES);
    cudaFuncSetAttribute(gemm_cp<2>, cudaFuncAttributeMaxDynamicSharedMemorySize, SMEM_BYTES);
    cudaFuncSetAttribute(gemm_cp<3>, cudaFuncAttributeMaxDynamicSharedMemorySize, SMEM_BYTES);

    // resolve device-symbol addresses (host API, graph-capture safe)
    __half *xh, *wguh, *wdh, *sguh, *sdh;
    cudaGetSymbolAddress((void**)&xh,   g_xh);
    cudaGetSymbolAddress((void**)&wguh, g_wguh);
    cudaGetSymbolAddress((void**)&wdh,  g_wdh);
    cudaGetSymbolAddress((void**)&sguh, g_sguh);
    cudaGetSymbolAddress((void**)&sdh,  g_sdh);

    // fp16 conversion passes
    f2h_kernel<<<(4194304 / 8 + 255) / 256, 256>>>(x, xh, 4194304 / 8);
    f2h_kernel<<<(int)((184549376LL / 8 + 255) / 256), 256>>>(wgu, wguh, 184549376LL / 8);
    f2h_kernel<<<(int)((92274688LL / 8 + 255) / 256), 256>>>(wd, wdh, 92274688LL / 8);
    f2h_kernel<<<(23068672 / 8 + 255) / 256, 256>>>(sgu, sguh, 23068672 / 8);
    f2h_kernel<<<(11534336 / 8 + 255) / 256, 256>>>(sd, sdh, 11534336 / 8);

    // router + deterministic bucketing
    router_kernel<<<T_, 256>>>(x, gw, sg);
    count_scan_kernel<<<1, 256>>>();
    bucket_kernel<<<E_, 32>>>();

    // routed experts (grouped, gathered rows)  [grid: m fastest for B reuse]
    gemm_cp<2><<<dim3(T_ / BM, 2 * I_ / BN, E_), 256, SMEM_BYTES>>>(wguh, nullptr);
    silu_mul_kernel<<<(T_ * TK_ * I_ / 4 + 255) / 256, 256>>>(T_ * TK_, I_);
    gemm_cp<3><<<dim3(T_ / BM, H_ / BN, E_), 256, SMEM_BYTES>>>(wdh, nullptr);

    // shared expert (dense) -> writes out = shared (sigmoid-gated)
    gemm_cp<0><<<dim3(T_ / BM, 2 * IS_ / BN, 1), 256, SMEM_BYTES>>>(sguh, nullptr);
    silu_mul_kernel<<<(T_ * IS_ / 4 + 255) / 256, 256>>>(T_, IS_);
    gemm_cp<1><<<dim3(T_ / BM, H_ / BN, 1), 256, SMEM_BYTES>>>(sdh, out);

    // out += routed combine
    reduce_kernel<<<T_ * H_ / 4 / 256, 256>>>(out);
}